// round 1
// baseline (speedup 1.0000x reference)
#include <cuda_runtime.h>
#include <cstdint>
#include <math.h>

// Problem dims (fixed by the reference)
#define HID   2560
#define SEQ   2048
#define BATCH 4
#define IND   2048
#define OUTD  2048
#define MROWS (BATCH * SEQ)   // 8192

// ---------------------------------------------------------------------------
// Scratch (device globals -- no cudaMalloc allowed)
// ---------------------------------------------------------------------------
__device__ float g_left[(size_t)MROWS * HID];  // gelu(x@Wl + bl)
__device__ float g_rin [(size_t)MROWS * HID];  // x@Wr + br
__device__ float g_conv[(size_t)MROWS * HID];  // causal depthwise conv
__device__ float g_ra  [(size_t)MROWS * HID];  // sigmoid(conv@Wa+ba) -> a
__device__ float g_ri  [(size_t)MROWS * HID];  // sigmoid(conv@Wi+bi) -> drive
__device__ float g_y   [(size_t)MROWS * HID];  // left * h

// ---------------------------------------------------------------------------
// tf32 helpers
// ---------------------------------------------------------------------------
__device__ __forceinline__ uint32_t f2tf32(float x) {
    uint32_t r;
    asm("cvt.rna.tf32.f32 %0, %1;" : "=r"(r) : "f"(x));
    return r;
}

__device__ __forceinline__ void mma8(float* d, const uint32_t* a, const uint32_t* b) {
    asm volatile(
        "mma.sync.aligned.m16n8k8.row.col.f32.tf32.tf32.f32 "
        "{%0,%1,%2,%3},{%4,%5,%6,%7},{%8,%9},{%0,%1,%2,%3};\n"
        : "+f"(d[0]), "+f"(d[1]), "+f"(d[2]), "+f"(d[3])
        : "r"(a[0]), "r"(a[1]), "r"(a[2]), "r"(a[3]),
          "r"(b[0]), "r"(b[1]));
}

// Epilogue activations: 0 = none, 1 = gelu(tanh approx, matches jax default), 2 = sigmoid
template <int ACT>
__device__ __forceinline__ float epi(float v) {
    if (ACT == 1) {
        float c = 0.7978845608028654f * (v + 0.044715f * v * v * v);
        return 0.5f * v * (1.0f + tanhf(c));
    } else if (ACT == 2) {
        return 1.0f / (1.0f + expf(-v));
    }
    return v;
}

// ---------------------------------------------------------------------------
// tf32 tensor-core GEMM: C[M,N] = act(A[M,K] @ B[K,N] + bias[N])
// Block 128x128x32, 256 threads (8 warps as 2x4), warp tile 64x32,
// mma m16n8k8. All dims here are multiples of 128/32 -> no bounds checks.
// Shared layouts are bank-conflict-free for both STS and fragment LDS.
// ---------------------------------------------------------------------------
template <int ACT>
__global__ __launch_bounds__(256, 2)
void gemm_tf32(const float* __restrict__ A, const float* __restrict__ Bm,
               const float* __restrict__ bias, float* __restrict__ C,
               int M, int N, int K)
{
    __shared__ uint32_t As[128][36];   // bank = (4m + k) & 31 : conflict-free
    __shared__ uint32_t Bs[32][136];   // bank = (8k + n) & 31 : conflict-free

    const int tid  = threadIdx.x;
    const int lane = tid & 31;
    const int warp = tid >> 5;
    const int wm   = (warp >> 2) * 64;   // warp row offset in block
    const int wn   = (warp & 3) * 32;    // warp col offset in block
    const int bM   = blockIdx.y * 128;
    const int bN   = blockIdx.x * 128;

    float acc[4][4][4];
#pragma unroll
    for (int i = 0; i < 4; i++)
#pragma unroll
        for (int j = 0; j < 4; j++)
#pragma unroll
            for (int k = 0; k < 4; k++) acc[i][j][k] = 0.0f;

    const int arow = tid >> 3;          // 0..31
    const int acol = (tid & 7) << 2;    // 0,4,..,28
    const int brow = tid >> 5;          // 0..7
    const int bcol = (tid & 31) << 2;   // 0,4,..,124

    for (int k0 = 0; k0 < K; k0 += 32) {
        // global -> shared (with tf32 RNA rounding)
#pragma unroll
        for (int r = 0; r < 128; r += 32) {
            float4 v = *(const float4*)(A + (size_t)(bM + arow + r) * K + (k0 + acol));
            As[arow + r][acol + 0] = f2tf32(v.x);
            As[arow + r][acol + 1] = f2tf32(v.y);
            As[arow + r][acol + 2] = f2tf32(v.z);
            As[arow + r][acol + 3] = f2tf32(v.w);
        }
#pragma unroll
        for (int r = 0; r < 32; r += 8) {
            float4 v = *(const float4*)(Bm + (size_t)(k0 + brow + r) * N + (bN + bcol));
            Bs[brow + r][bcol + 0] = f2tf32(v.x);
            Bs[brow + r][bcol + 1] = f2tf32(v.y);
            Bs[brow + r][bcol + 2] = f2tf32(v.z);
            Bs[brow + r][bcol + 3] = f2tf32(v.w);
        }
        __syncthreads();

#pragma unroll
        for (int ks = 0; ks < 4; ks++) {
            const int kk = ks * 8 + (lane & 3);
            uint32_t af[4][4], bf[4][2];
#pragma unroll
            for (int mt = 0; mt < 4; mt++) {
                int m = wm + mt * 16 + (lane >> 2);
                af[mt][0] = As[m][kk];
                af[mt][1] = As[m + 8][kk];
                af[mt][2] = As[m][kk + 4];
                af[mt][3] = As[m + 8][kk + 4];
            }
#pragma unroll
            for (int nt = 0; nt < 4; nt++) {
                int n = wn + nt * 8 + (lane >> 2);
                bf[nt][0] = Bs[kk][n];
                bf[nt][1] = Bs[kk + 4][n];
            }
#pragma unroll
            for (int mt = 0; mt < 4; mt++)
#pragma unroll
                for (int nt = 0; nt < 4; nt++)
                    mma8(acc[mt][nt], af[mt], bf[nt]);
        }
        __syncthreads();
    }

    // epilogue: bias + activation, float2 stores
#pragma unroll
    for (int mt = 0; mt < 4; mt++) {
        int row = bM + wm + mt * 16 + (lane >> 2);
#pragma unroll
        for (int nt = 0; nt < 4; nt++) {
            int col = bN + wn + nt * 8 + ((lane & 3) << 1);
            float b0 = bias[col], b1 = bias[col + 1];
            float2 v0 = make_float2(epi<ACT>(acc[mt][nt][0] + b0),
                                    epi<ACT>(acc[mt][nt][1] + b1));
            *(float2*)(C + (size_t)row * N + col) = v0;
            float2 v1 = make_float2(epi<ACT>(acc[mt][nt][2] + b0),
                                    epi<ACT>(acc[mt][nt][3] + b1));
            *(float2*)(C + (size_t)(row + 8) * N + col) = v1;
        }
    }
}

// ---------------------------------------------------------------------------
// Causal depthwise conv1d, kernel width 4, left pad 3:
// conv[b,s,h] = conv_b[h] + sum_{k=0..3} w[k,0,h] * rin[b, s-3+k, h]
// ---------------------------------------------------------------------------
__global__ void conv_kernel(const float* __restrict__ w, const float* __restrict__ cb)
{
    int i = blockIdx.x * blockDim.x + threadIdx.x;  // over MROWS*HID
    int h = i % HID;
    int s = (i / HID) % SEQ;
    const float* base = g_rin + (size_t)i;
    float acc = cb[h];
#pragma unroll
    for (int k = 0; k < 4; k++) {
        int t = s - 3 + k;
        if (t >= 0) acc += w[k * HID + h] * base[(long)(k - 3) * HID];
    }
    g_conv[i] = acc;
}

// ---------------------------------------------------------------------------
// RG-LRU gate math: inputs r (in g_ra), i (in g_ri), u (g_conv).
// a = exp(-8*softplus(-lam)*r); beta = sqrt(max(1-a^2,1e-12)); drive = beta*i*u
// ---------------------------------------------------------------------------
__global__ void gate_kernel(const float* __restrict__ lam)
{
    int i = blockIdx.x * blockDim.x + threadIdx.x;
    int h = i % HID;
    float r  = g_ra[i];
    float ii = g_ri[i];
    float u  = g_conv[i];
    float lamv = lam[h];
    float sp = log1pf(expf(-lamv));          // softplus(-lam)
    float la = -8.0f * sp * r;               // log a  (<= 0)
    float a  = expf(la);
    float beta = sqrtf(fmaxf(1.0f - expf(2.0f * la), 1e-12f));
    g_ra[i] = a;
    g_ri[i] = beta * ii * u;
}

// ---------------------------------------------------------------------------
// Sequential scan over S per (b,h), fused with y = left * h.
// 10240 independent recurrences; unrolled for MLP.
// ---------------------------------------------------------------------------
__global__ void scan_kernel()
{
    int idx = blockIdx.x * blockDim.x + threadIdx.x;  // over BATCH*HID
    if (idx >= BATCH * HID) return;
    int b = idx / HID, h = idx % HID;
    size_t off = (size_t)b * SEQ * HID + h;
    const float* ap = g_ra   + off;
    const float* dp = g_ri   + off;
    const float* lp = g_left + off;
    float*       yp = g_y    + off;
    float hs = 0.0f;
#pragma unroll 8
    for (int s = 0; s < SEQ; s++) {
        size_t o = (size_t)s * HID;
        float a = ap[o];
        float d = dp[o];
        hs = fmaf(a, hs, d);
        yp[o] = lp[o] * hs;
    }
}

// ---------------------------------------------------------------------------
// Launch
// ---------------------------------------------------------------------------
extern "C" void kernel_launch(void* const* d_in, const int* in_sizes, int n_in,
                              void* d_out, int out_size)
{
    const float* x      = (const float*)d_in[0];
    const float* Wl     = (const float*)d_in[1];
    const float* bl     = (const float*)d_in[2];
    const float* Wr     = (const float*)d_in[3];
    const float* br     = (const float*)d_in[4];
    const float* conv_w = (const float*)d_in[5];
    const float* conv_b = (const float*)d_in[6];
    const float* Wa     = (const float*)d_in[7];
    const float* ba     = (const float*)d_in[8];
    const float* Wi     = (const float*)d_in[9];
    const float* bi     = (const float*)d_in[10];
    const float* lam    = (const float*)d_in[11];
    const float* Wo     = (const float*)d_in[12];
    const float* bo     = (const float*)d_in[13];
    float* out = (float*)d_out;

    float *p_left, *p_rin, *p_conv, *p_ra, *p_ri, *p_y;
    cudaGetSymbolAddress((void**)&p_left, g_left);
    cudaGetSymbolAddress((void**)&p_rin,  g_rin);
    cudaGetSymbolAddress((void**)&p_conv, g_conv);
    cudaGetSymbolAddress((void**)&p_ra,   g_ra);
    cudaGetSymbolAddress((void**)&p_ri,   g_ri);
    cudaGetSymbolAddress((void**)&p_y,    g_y);

    dim3 blk(256);
    dim3 gridH(HID / 128, MROWS / 128);   // N=2560 GEMMs
    dim3 gridO(OUTD / 128, MROWS / 128);  // N=2048 GEMM
    int ew_blocks = (MROWS * HID) / 256;  // elementwise grids

    // 1) left = gelu(x@Wl+bl); rin = x@Wr+br
    gemm_tf32<1><<<gridH, blk>>>(x, Wl, bl, p_left, MROWS, HID, IND);
    gemm_tf32<0><<<gridH, blk>>>(x, Wr, br, p_rin,  MROWS, HID, IND);

    // 2) causal depthwise conv
    conv_kernel<<<ew_blocks, blk>>>(conv_w, conv_b);

    // 3) gates: r = sigmoid(conv@Wa+ba), i = sigmoid(conv@Wi+bi), then a/drive
    gemm_tf32<2><<<gridH, blk>>>(p_conv, Wa, ba, p_ra, MROWS, HID, HID);
    gemm_tf32<2><<<gridH, blk>>>(p_conv, Wi, bi, p_ri, MROWS, HID, HID);
    gate_kernel<<<ew_blocks, blk>>>(lam);

    // 4) recurrent scan fused with y = left * h
    scan_kernel<<<(BATCH * HID + 255) / 256, blk>>>();

    // 5) out = y@Wo + bo
    gemm_tf32<0><<<gridO, blk>>>(p_y, Wo, bo, out, MROWS, OUTD, HID);
}

// round 3
// speedup vs baseline: 1.8775x; 1.8775x over previous
#include <cuda_runtime.h>
#include <cstdint>
#include <math.h>

// Problem dims (fixed by the reference)
#define HID   2560
#define SEQ   2048
#define BATCH 4
#define IND   2048
#define OUTD  2048
#define MROWS (BATCH * SEQ)   // 8192

#define NCHUNK 16
#define CLEN   (SEQ / NCHUNK) // 128

// ---------------------------------------------------------------------------
// Scratch (device globals -- no cudaMalloc allowed)
// ---------------------------------------------------------------------------
__device__ float g_left[(size_t)MROWS * HID];
__device__ float g_rin [(size_t)MROWS * HID];
__device__ float g_conv[(size_t)MROWS * HID];   // tf32-rounded conv output
__device__ float g_ra  [(size_t)MROWS * HID];   // r then a
__device__ float g_ri  [(size_t)MROWS * HID];   // drive
__device__ float g_y   [(size_t)MROWS * HID];   // tf32-rounded left*h
__device__ float g_xr  [(size_t)MROWS * IND];   // tf32-rounded x
__device__ float g_wl  [(size_t)IND * HID];
__device__ float g_wr  [(size_t)IND * HID];
__device__ float g_wa  [(size_t)HID * HID];
__device__ float g_wi  [(size_t)HID * HID];
__device__ float g_wo  [(size_t)HID * OUTD];
__device__ float g_cp  [BATCH * NCHUNK * HID];
__device__ float g_ch  [BATCH * NCHUNK * HID];
__device__ float g_hin [BATCH * NCHUNK * HID];
__device__ float g_lamc[HID];                   // -8*softplus(-lam)

// ---------------------------------------------------------------------------
// helpers
// ---------------------------------------------------------------------------
__device__ __forceinline__ uint32_t f2tf32(float x) {
    uint32_t r;
    asm("cvt.rna.tf32.f32 %0, %1;" : "=r"(r) : "f"(x));
    return r;
}
__device__ __forceinline__ float rnd_tf32(float x) {
    return __uint_as_float(f2tf32(x));
}
__device__ __forceinline__ uint32_t smem_u32(const void* p) {
    uint32_t a;
    asm("{ .reg .u64 t; cvta.to.shared.u64 t, %1; cvt.u32.u64 %0, t; }" : "=r"(a) : "l"(p));
    return a;
}
__device__ __forceinline__ void cp16(uint32_t dst, const void* src) {
    asm volatile("cp.async.cg.shared.global [%0], [%1], 16;" :: "r"(dst), "l"(src));
}
#define CP_COMMIT() asm volatile("cp.async.commit_group;" ::: "memory")
#define CP_WAIT1()  asm volatile("cp.async.wait_group 1;" ::: "memory")

__device__ __forceinline__ void ldsm_x4(uint32_t* r, uint32_t addr) {
    asm volatile("ldmatrix.sync.aligned.m8n8.x4.shared.b16 {%0,%1,%2,%3}, [%4];"
                 : "=r"(r[0]), "=r"(r[1]), "=r"(r[2]), "=r"(r[3]) : "r"(addr));
}
__device__ __forceinline__ void mma8(float* d, const uint32_t* a, const uint32_t* b) {
    asm volatile(
        "mma.sync.aligned.m16n8k8.row.col.f32.tf32.tf32.f32 "
        "{%0,%1,%2,%3},{%4,%5,%6,%7},{%8,%9},{%0,%1,%2,%3};\n"
        : "+f"(d[0]), "+f"(d[1]), "+f"(d[2]), "+f"(d[3])
        : "r"(a[0]), "r"(a[1]), "r"(a[2]), "r"(a[3]),
          "r"(b[0]), "r"(b[1]));
}

template <int ACT>
__device__ __forceinline__ float epi(float v) {
    if (ACT == 1) {   // gelu tanh approx (jax default)
        float c = 0.7978845608028654f * (v + 0.044715f * v * v * v);
        return 0.5f * v * (1.0f + tanhf(c));
    } else if (ACT == 2) {  // sigmoid
        return 1.0f / (1.0f + expf(-v));
    }
    return v;
}

// ---------------------------------------------------------------------------
// tf32 tensor-core GEMM: C = act(A[M,K] @ B[K,N] + bias)
// Inputs must be pre-rounded to tf32 (raw cp.async staging).
// CTA 128x128, k-chunk 32, 3-stage cp.async pipeline, 256 threads (8 warps
// 2x4, warp tile 64x32). A fragments via ldmatrix.x4 on SW128 layout.
// ACT==3: fused RG-LRU gate epilogue (Wi gemm): reads r (Rbuf) and u (Ubuf),
//         writes a -> Aout, drive -> C.
// smem: A stages [3][128][32] tf32 @0 (16KB each, SW128),
//       B stages [3][32][136] float @49152 (17408B each, padded).
// ---------------------------------------------------------------------------
#define SMB_OFF 49152
#define SM_BYTES (49152 + 3 * 17408)

template <int ACT>
__global__ void __launch_bounds__(256, 2)
gemm_cp(const float* __restrict__ A, const float* __restrict__ B,
        const float* __restrict__ bias, float* __restrict__ C,
        int M, int N, int K,
        const float* __restrict__ Rbuf, const float* __restrict__ Ubuf,
        const float* __restrict__ lamc, float* __restrict__ Aout)
{
    extern __shared__ char sm[];
    const int tid  = threadIdx.x;
    const int lane = tid & 31;
    const int warp = tid >> 5;
    const int wm   = (warp >> 2) * 64;
    const int wn   = (warp & 3) * 32;
    const int bM   = blockIdx.y * 128;
    const int bN   = blockIdx.x * 128;
    const uint32_t smb = smem_u32(sm);
    const int NK = K >> 5;

    float acc[4][4][4];
#pragma unroll
    for (int i = 0; i < 4; i++)
#pragma unroll
        for (int j = 0; j < 4; j++)
#pragma unroll
            for (int k = 0; k < 4; k++) acc[i][j][k] = 0.0f;

    // staging index precompute
    const int ar = tid >> 3;            // A row 0..127 (wait: 256 threads -> rows 0..31? no: idx below)
    const int ac = tid & 7;             // A 16B-chunk 0..7
    const int bk = tid >> 5;            // B k-subrow base
    const int bn4 = (tid & 31) << 2;    // B n offset (words)

    auto load_stage = [&](int kc, int s) {
        const int k0 = kc << 5;
        // A: 128 rows x 32 tf32 (8 chunks of 16B per row), 1024 chunks, 4/thread
#pragma unroll
        for (int i = 0; i < 4; i++) {
            int idx = tid + (i << 8);
            int r = idx >> 3, c = idx & 7;
            uint32_t o = (uint32_t)(r * 128 + c * 16);
            o ^= (uint32_t)((r & 7) << 4);                 // SW128
            cp16(smb + (uint32_t)s * 16384u + o,
                 A + (size_t)(bM + r) * K + k0 + (c << 2));
        }
        // B: 32 k-rows x 128 n, padded row stride 136 words
#pragma unroll
        for (int i = 0; i < 4; i++) {
            int idx = tid + (i << 8);
            int kk = idx >> 5, n4 = (idx & 31) << 2;
            cp16(smb + SMB_OFF + (uint32_t)s * 17408u + (uint32_t)((kk * 136 + n4) << 2),
                 B + (size_t)(k0 + kk) * N + bN + n4);
        }
    };

    // prologue: stages 0,1
    load_stage(0, 0); CP_COMMIT();
    load_stage(1, 1); CP_COMMIT();

    const int jmat = lane >> 3;       // ldmatrix matrix id
    const int r8   = lane & 7;        // ldmatrix row within matrix

    int stage = 0;
    for (int kc = 0; kc < NK; kc++) {
        CP_WAIT1();
        __syncthreads();
        // issue stage kc+2 (overlaps with mma below)
        if (kc + 2 < NK) load_stage(kc + 2, (stage + 2) % 3);
        CP_COMMIT();

        const uint32_t aBase = smb + (uint32_t)stage * 16384u;
        float* Bsh = reinterpret_cast<float*>(sm + SMB_OFF + stage * 17408);

#pragma unroll
        for (int ks = 0; ks < 4; ks++) {
            uint32_t af[4][4];
#pragma unroll
            for (int mt = 0; mt < 4; mt++) {
                int row = wm + mt * 16 + ((jmat & 1) << 3) + r8;
                uint32_t o = (uint32_t)(row * 128 + ks * 32 + ((jmat >> 1) << 4));
                o ^= (uint32_t)(r8 << 4);
                ldsm_x4(af[mt], aBase + o);
            }
            uint32_t bf[4][2];
            const int kk = ks * 8 + (lane & 3);
#pragma unroll
            for (int nt = 0; nt < 4; nt++) {
                int n = wn + nt * 8 + (lane >> 2);
                bf[nt][0] = __float_as_uint(Bsh[kk * 136 + n]);
                bf[nt][1] = __float_as_uint(Bsh[(kk + 4) * 136 + n]);
            }
#pragma unroll
            for (int mt = 0; mt < 4; mt++)
#pragma unroll
                for (int nt = 0; nt < 4; nt++)
                    mma8(acc[mt][nt], af[mt], bf[nt]);
        }
        stage = (stage + 1) % 3;
    }

    // --------------------------- epilogue ---------------------------------
#pragma unroll
    for (int mt = 0; mt < 4; mt++) {
        int row0 = bM + wm + mt * 16 + (lane >> 2);
#pragma unroll
        for (int nt = 0; nt < 4; nt++) {
            int col = bN + wn + nt * 8 + ((lane & 3) << 1);
            float b0 = bias[col], b1 = bias[col + 1];
            if (ACT == 3) {
                float lc0 = lamc[col], lc1 = lamc[col + 1];
#pragma unroll
                for (int rr = 0; rr < 2; rr++) {
                    size_t idx = (size_t)(row0 + rr * 8) * N + col;
                    float v0 = acc[mt][nt][rr * 2 + 0] + b0;
                    float v1 = acc[mt][nt][rr * 2 + 1] + b1;
                    float i0 = 1.0f / (1.0f + expf(-v0));
                    float i1 = 1.0f / (1.0f + expf(-v1));
                    float2 rv = *(const float2*)(Rbuf + idx);
                    float2 uv = *(const float2*)(Ubuf + idx);
                    float a0 = expf(lc0 * rv.x);
                    float a1 = expf(lc1 * rv.y);
                    float be0 = sqrtf(fmaxf(1.0f - a0 * a0, 1e-12f));
                    float be1 = sqrtf(fmaxf(1.0f - a1 * a1, 1e-12f));
                    *(float2*)(Aout + idx) = make_float2(a0, a1);
                    *(float2*)(C + idx) = make_float2(be0 * i0 * uv.x, be1 * i1 * uv.y);
                }
            } else {
                float2 v0 = make_float2(epi<ACT>(acc[mt][nt][0] + b0),
                                        epi<ACT>(acc[mt][nt][1] + b1));
                *(float2*)(C + (size_t)row0 * N + col) = v0;
                float2 v1 = make_float2(epi<ACT>(acc[mt][nt][2] + b0),
                                        epi<ACT>(acc[mt][nt][3] + b1));
                *(float2*)(C + (size_t)(row0 + 8) * N + col) = v1;
            }
        }
    }
}

// ---------------------------------------------------------------------------
// tf32 rounding copy (n multiple of 1024; float4 per thread)
// ---------------------------------------------------------------------------
__global__ void round_tf32(const float* __restrict__ src, float* __restrict__ dst)
{
    int i = (blockIdx.x * blockDim.x + threadIdx.x) * 4;
    float4 v = *(const float4*)(src + i);
    v.x = rnd_tf32(v.x); v.y = rnd_tf32(v.y);
    v.z = rnd_tf32(v.z); v.w = rnd_tf32(v.w);
    *(float4*)(dst + i) = v;
}

// ---------------------------------------------------------------------------
// Causal depthwise conv1d (width 4, left pad 3); writes tf32-rounded output
// ---------------------------------------------------------------------------
__global__ void conv_kernel(const float* __restrict__ w, const float* __restrict__ cb)
{
    int i = blockIdx.x * blockDim.x + threadIdx.x;
    int h = i % HID;
    int s = (i / HID) % SEQ;
    const float* base = g_rin + (size_t)i;
    float acc = cb[h];
#pragma unroll
    for (int k = 0; k < 4; k++) {
        int t = s - 3 + k;
        if (t >= 0) acc = fmaf(w[k * HID + h], base[(long)(k - 3) * HID], acc);
    }
    g_conv[i] = rnd_tf32(acc);
}

__global__ void lamc_kernel(const float* __restrict__ lam)
{
    int h = blockIdx.x * blockDim.x + threadIdx.x;
    if (h < HID) g_lamc[h] = -8.0f * log1pf(expf(-lam[h]));
}

// ---------------------------------------------------------------------------
// Chunked scan (3 passes), chunk length 128, 16 chunks/sequence.
// ---------------------------------------------------------------------------
__global__ void scan_pass1()
{
    int idx = blockIdx.x * blockDim.x + threadIdx.x;
    int h = idx % HID;
    int t = idx / HID;
    int c = t % NCHUNK;
    int b = t / NCHUNK;
    size_t base = ((size_t)b * SEQ + (size_t)c * CLEN) * HID + h;
    float P = 1.0f, hs = 0.0f;
#pragma unroll 4
    for (int s = 0; s < CLEN; s++) {
        size_t o = base + (size_t)s * HID;
        float a = g_ra[o], d = g_ri[o];
        P *= a;
        hs = fmaf(a, hs, d);
    }
    size_t oo = ((size_t)b * NCHUNK + c) * HID + h;
    g_cp[oo] = P;
    g_ch[oo] = hs;
}

__global__ void scan_pass2()
{
    int idx = blockIdx.x * blockDim.x + threadIdx.x;
    if (idx >= BATCH * HID) return;
    int b = idx / HID, h = idx % HID;
    float hin = 0.0f;
#pragma unroll
    for (int c = 0; c < NCHUNK; c++) {
        size_t oo = ((size_t)b * NCHUNK + c) * HID + h;
        g_hin[oo] = hin;
        hin = fmaf(g_cp[oo], hin, g_ch[oo]);
    }
}

__global__ void scan_pass3()
{
    int idx = blockIdx.x * blockDim.x + threadIdx.x;
    int h = idx % HID;
    int t = idx / HID;
    int c = t % NCHUNK;
    int b = t / NCHUNK;
    size_t base = ((size_t)b * SEQ + (size_t)c * CLEN) * HID + h;
    float hs = g_hin[((size_t)b * NCHUNK + c) * HID + h];
#pragma unroll 4
    for (int s = 0; s < CLEN; s++) {
        size_t o = base + (size_t)s * HID;
        float a = g_ra[o], d = g_ri[o];
        hs = fmaf(a, hs, d);
        g_y[o] = rnd_tf32(g_left[o] * hs);
    }
}

// ---------------------------------------------------------------------------
// Launch
// ---------------------------------------------------------------------------
extern "C" void kernel_launch(void* const* d_in, const int* in_sizes, int n_in,
                              void* d_out, int out_size)
{
    const float* x      = (const float*)d_in[0];
    const float* Wl     = (const float*)d_in[1];
    const float* bl     = (const float*)d_in[2];
    const float* Wr     = (const float*)d_in[3];
    const float* br     = (const float*)d_in[4];
    const float* conv_w = (const float*)d_in[5];
    const float* conv_b = (const float*)d_in[6];
    const float* Wa     = (const float*)d_in[7];
    const float* ba     = (const float*)d_in[8];
    const float* Wi     = (const float*)d_in[9];
    const float* bi     = (const float*)d_in[10];
    const float* lam    = (const float*)d_in[11];
    const float* Wo     = (const float*)d_in[12];
    const float* bo     = (const float*)d_in[13];
    float* out = (float*)d_out;

    float *p_left, *p_rin, *p_conv, *p_ra, *p_ri, *p_y, *p_xr;
    float *p_wl, *p_wr, *p_wa, *p_wi, *p_wo, *p_lamc;
    cudaGetSymbolAddress((void**)&p_left, g_left);
    cudaGetSymbolAddress((void**)&p_rin,  g_rin);
    cudaGetSymbolAddress((void**)&p_conv, g_conv);
    cudaGetSymbolAddress((void**)&p_ra,   g_ra);
    cudaGetSymbolAddress((void**)&p_ri,   g_ri);
    cudaGetSymbolAddress((void**)&p_y,    g_y);
    cudaGetSymbolAddress((void**)&p_xr,   g_xr);
    cudaGetSymbolAddress((void**)&p_wl,   g_wl);
    cudaGetSymbolAddress((void**)&p_wr,   g_wr);
    cudaGetSymbolAddress((void**)&p_wa,   g_wa);
    cudaGetSymbolAddress((void**)&p_wi,   g_wi);
    cudaGetSymbolAddress((void**)&p_wo,   g_wo);
    cudaGetSymbolAddress((void**)&p_lamc, g_lamc);

    cudaFuncSetAttribute(gemm_cp<0>, cudaFuncAttributeMaxDynamicSharedMemorySize, SM_BYTES);
    cudaFuncSetAttribute(gemm_cp<1>, cudaFuncAttributeMaxDynamicSharedMemorySize, SM_BYTES);
    cudaFuncSetAttribute(gemm_cp<2>, cudaFuncAttributeMaxDynamicSharedMemorySize, SM_BYTES);
    cudaFuncSetAttribute(gemm_cp<3>, cudaFuncAttributeMaxDynamicSharedMemorySize, SM_BYTES);

    dim3 blk(256);
    dim3 gridH(HID / 128, MROWS / 128);
    dim3 gridO(OUTD / 128, MROWS / 128);
    int ew_blocks = (MROWS * HID) / 256;
    int sc_blocks = (BATCH * NCHUNK * HID) / 256;

    // 0) pre-round GEMM operands to tf32
    round_tf32<<<(MROWS * IND) / 1024, blk>>>(x,  p_xr);
    round_tf32<<<(IND * HID) / 1024, blk>>>(Wl, p_wl);
    round_tf32<<<(IND * HID) / 1024, blk>>>(Wr, p_wr);
    round_tf32<<<(HID * HID) / 1024, blk>>>(Wa, p_wa);
    round_tf32<<<(HID * HID) / 1024, blk>>>(Wi, p_wi);
    round_tf32<<<(HID * OUTD) / 1024, blk>>>(Wo, p_wo);
    lamc_kernel<<<(HID + 255) / 256, blk>>>(lam);

    // 1) left = gelu(x@Wl+bl); rin = x@Wr+br
    gemm_cp<1><<<gridH, blk, SM_BYTES>>>(p_xr, p_wl, bl, p_left, MROWS, HID, IND,
                                         nullptr, nullptr, nullptr, nullptr);
    gemm_cp<0><<<gridH, blk, SM_BYTES>>>(p_xr, p_wr, br, p_rin,  MROWS, HID, IND,
                                         nullptr, nullptr, nullptr, nullptr);

    // 2) causal depthwise conv (tf32-rounded output)
    conv_kernel<<<ew_blocks, blk>>>(conv_w, conv_b);

    // 3) r = sigmoid(conv@Wa+ba); then Wi-GEMM with fused gate epilogue
    gemm_cp<2><<<gridH, blk, SM_BYTES>>>(p_conv, p_wa, ba, p_ra, MROWS, HID, HID,
                                         nullptr, nullptr, nullptr, nullptr);
    gemm_cp<3><<<gridH, blk, SM_BYTES>>>(p_conv, p_wi, bi, p_ri, MROWS, HID, HID,
                                         p_ra, p_conv, p_lamc, p_ra);

    // 4) chunked scan + y = round(left*h)
    scan_pass1<<<sc_blocks, blk>>>();
    scan_pass2<<<(BATCH * HID + 255) / 256, blk>>>();
    scan_pass3<<<sc_blocks, blk>>>();

    // 5) out = y@Wo + bo
    gemm_cp<0><<<gridO, blk, SM_BYTES>>>(p_y, p_wo, bo, out, MROWS, OUTD, HID,
                                         nullptr, nullptr, nullptr, nullptr);
}

// round 4
// speedup vs baseline: 2.0742x; 1.1048x over previous
#include <cuda_runtime.h>
#include <cstdint>
#include <math.h>

// Problem dims (fixed by the reference)
#define HID   2560
#define SEQ   2048
#define BATCH 4
#define IND   2048
#define OUTD  2048
#define MROWS (BATCH * SEQ)   // 8192

#define NCHUNK 16
#define CLEN   (SEQ / NCHUNK) // 128

// ---------------------------------------------------------------------------
// Scratch (device globals -- no cudaMalloc allowed)
// ---------------------------------------------------------------------------
__device__ float g_left[(size_t)MROWS * HID];
__device__ float g_rin [(size_t)MROWS * HID];
__device__ float g_conv[(size_t)MROWS * HID];   // tf32-rounded conv output
__device__ float g_ra  [(size_t)MROWS * HID];   // r then a
__device__ float g_ri  [(size_t)MROWS * HID];   // drive
__device__ float g_y   [(size_t)MROWS * HID];   // tf32-rounded left*h
__device__ float g_xr  [(size_t)MROWS * IND];   // tf32-rounded x
__device__ float g_wl  [(size_t)IND * HID];     // transposed [HID][IND]
__device__ float g_wr  [(size_t)IND * HID];     // transposed [HID][IND]
__device__ float g_wa  [(size_t)HID * HID];     // transposed
__device__ float g_wi  [(size_t)HID * HID];     // transposed
__device__ float g_wo  [(size_t)HID * OUTD];    // transposed [OUTD][HID]
__device__ float g_cp  [BATCH * NCHUNK * HID];
__device__ float g_ch  [BATCH * NCHUNK * HID];
__device__ float g_hin [BATCH * NCHUNK * HID];
__device__ float g_lamc[HID];                   // -8*softplus(-lam)

// ---------------------------------------------------------------------------
// helpers
// ---------------------------------------------------------------------------
__device__ __forceinline__ uint32_t f2tf32(float x) {
    uint32_t r;
    asm("cvt.rna.tf32.f32 %0, %1;" : "=r"(r) : "f"(x));
    return r;
}
__device__ __forceinline__ float rnd_tf32(float x) {
    return __uint_as_float(f2tf32(x));
}
__device__ __forceinline__ uint32_t smem_u32(const void* p) {
    uint32_t a;
    asm("{ .reg .u64 t; cvta.to.shared.u64 t, %1; cvt.u32.u64 %0, t; }" : "=r"(a) : "l"(p));
    return a;
}
__device__ __forceinline__ void cp16(uint32_t dst, const void* src) {
    asm volatile("cp.async.cg.shared.global [%0], [%1], 16;" :: "r"(dst), "l"(src));
}
#define CP_COMMIT() asm volatile("cp.async.commit_group;" ::: "memory")
#define CP_WAIT1()  asm volatile("cp.async.wait_group 1;" ::: "memory")

__device__ __forceinline__ void ldsm_x4(uint32_t* r, uint32_t addr) {
    asm volatile("ldmatrix.sync.aligned.m8n8.x4.shared.b16 {%0,%1,%2,%3}, [%4];"
                 : "=r"(r[0]), "=r"(r[1]), "=r"(r[2]), "=r"(r[3]) : "r"(addr));
}
__device__ __forceinline__ void mma8(float* d, const uint32_t* a, const uint32_t* b) {
    asm volatile(
        "mma.sync.aligned.m16n8k8.row.col.f32.tf32.tf32.f32 "
        "{%0,%1,%2,%3},{%4,%5,%6,%7},{%8,%9},{%0,%1,%2,%3};\n"
        : "+f"(d[0]), "+f"(d[1]), "+f"(d[2]), "+f"(d[3])
        : "r"(a[0]), "r"(a[1]), "r"(a[2]), "r"(a[3]),
          "r"(b[0]), "r"(b[1]));
}

__device__ __forceinline__ float gelu_f(float v) {
    float c = 0.7978845608028654f * (v + 0.044715f * v * v * v);
    return 0.5f * v * (1.0f + tanhf(c));
}
__device__ __forceinline__ float sigmoid_f(float v) {
    return 1.0f / (1.0f + expf(-v));
}

// ---------------------------------------------------------------------------
// tf32 tensor-core GEMM: C = act(A[M,K] @ Bt[N,K]^T + bias)
// B must be PRE-TRANSPOSED to [N][K] (and tf32-rounded); A tf32-rounded.
// CTA 128x128, k-chunk 32, 3-stage cp.async pipeline, 256 threads (8 warps
// 2x4, warp tile 64x32). Both operands via ldmatrix.x4 on SW128 layout:
// per k-step per warp = 4 A-LDSM + 2 B-LDSM for 16 HMMAs.
// ACT: 0 none, 1 gelu, 2 sigmoid,
//      3 = sigmoid + fused RG-LRU gate (reads Rbuf/Ubuf, writes Aout & C),
//      4 = dual output: first half of grid.x -> gelu into C, second half ->
//          none into C2 with B2/bias2 (Wl/Wr fusion).
// smem: A stages [3][128rows][128B] @0, B stages same @49152. Total 96KB.
// ---------------------------------------------------------------------------
#define SMB_OFF 49152
#define SM_BYTES 98304

template <int ACT>
__global__ void __launch_bounds__(256, 2)
gemm_tt(const float* __restrict__ A, const float* __restrict__ B,
        const float* __restrict__ bias, float* __restrict__ C,
        int M, int N, int K,
        const float* __restrict__ Rbuf, const float* __restrict__ Ubuf,
        const float* __restrict__ lamc, float* __restrict__ Aout,
        const float* B2, const float* bias2, float* C2)
{
    extern __shared__ char sm[];
    const int tid  = threadIdx.x;
    const int lane = tid & 31;
    const int warp = tid >> 5;
    const int wm   = (warp >> 2) * 64;
    const int wn   = (warp & 3) * 32;
    const int bM   = blockIdx.y * 128;
    const uint32_t smb = smem_u32(sm);
    const int NK = K >> 5;

    int bN;
    int act = ACT;
    if (ACT == 4) {
        int half = gridDim.x >> 1;
        if (blockIdx.x >= half) {
            B = B2; bias = bias2; C = C2; act = 0;
            bN = (blockIdx.x - half) * 128;
        } else {
            act = 1;
            bN = blockIdx.x * 128;
        }
    } else {
        bN = blockIdx.x * 128;
    }

    float acc[4][4][4];
#pragma unroll
    for (int i = 0; i < 4; i++)
#pragma unroll
        for (int j = 0; j < 4; j++)
#pragma unroll
            for (int k = 0; k < 4; k++) acc[i][j][k] = 0.0f;

    auto load_stage = [&](int kc, int s) {
        const int k0 = kc << 5;
        // A: 128 m-rows x 32 tf32 (128B rows, SW128)
#pragma unroll
        for (int i = 0; i < 4; i++) {
            int idx = tid + (i << 8);
            int r = idx >> 3, c = idx & 7;
            uint32_t o = (uint32_t)(r * 128 + c * 16);
            o ^= (uint32_t)((r & 7) << 4);
            cp16(smb + (uint32_t)s * 16384u + o,
                 A + (size_t)(bM + r) * K + k0 + (c << 2));
        }
        // B (pre-transposed [N][K]): 128 n-rows x 32 tf32, same layout
#pragma unroll
        for (int i = 0; i < 4; i++) {
            int idx = tid + (i << 8);
            int r = idx >> 3, c = idx & 7;
            uint32_t o = (uint32_t)(r * 128 + c * 16);
            o ^= (uint32_t)((r & 7) << 4);
            cp16(smb + SMB_OFF + (uint32_t)s * 16384u + o,
                 B + (size_t)(bN + r) * K + k0 + (c << 2));
        }
    };

    load_stage(0, 0); CP_COMMIT();
    load_stage(1, 1); CP_COMMIT();

    const int jmat = lane >> 3;       // 0..3
    const int r8   = lane & 7;

    int stage = 0;
    for (int kc = 0; kc < NK; kc++) {
        CP_WAIT1();
        __syncthreads();
        if (kc + 2 < NK) load_stage(kc + 2, (stage + 2) % 3);
        CP_COMMIT();

        const uint32_t aBase = smb + (uint32_t)stage * 16384u;
        const uint32_t bBase = smb + SMB_OFF + (uint32_t)stage * 16384u;

#pragma unroll
        for (int ks = 0; ks < 4; ks++) {
            // A fragments: 4x ldmatrix.x4 (m16k8 tiles for mt 0..3)
            uint32_t af[4][4];
#pragma unroll
            for (int mt = 0; mt < 4; mt++) {
                int row = wm + mt * 16 + ((jmat & 1) << 3) + r8;
                uint32_t o = (uint32_t)(row * 128 + ks * 32 + ((jmat >> 1) << 4));
                o ^= (uint32_t)(r8 << 4);
                ldsm_x4(af[mt], aBase + o);
            }
            // B fragments: 2x ldmatrix.x4, each covers 16 n (2 nt)
            uint32_t bf[4][2];
#pragma unroll
            for (int p = 0; p < 2; p++) {
                int nrow = wn + p * 16 + ((jmat >> 1) << 3) + r8;
                uint32_t o = (uint32_t)(nrow * 128 + ks * 32 + ((jmat & 1) << 4));
                o ^= (uint32_t)(r8 << 4);
                uint32_t t[4];
                ldsm_x4(t, bBase + o);
                bf[p * 2 + 0][0] = t[0]; bf[p * 2 + 0][1] = t[1];
                bf[p * 2 + 1][0] = t[2]; bf[p * 2 + 1][1] = t[3];
            }
#pragma unroll
            for (int mt = 0; mt < 4; mt++)
#pragma unroll
                for (int nt = 0; nt < 4; nt++)
                    mma8(acc[mt][nt], af[mt], bf[nt]);
        }
        stage = (stage + 1) % 3;
    }

    // --------------------------- epilogue ---------------------------------
#pragma unroll
    for (int mt = 0; mt < 4; mt++) {
        int row0 = bM + wm + mt * 16 + (lane >> 2);
#pragma unroll
        for (int nt = 0; nt < 4; nt++) {
            int col = bN + wn + nt * 8 + ((lane & 3) << 1);
            float b0 = bias[col], b1 = bias[col + 1];
            if (ACT == 3) {
                float lc0 = lamc[col], lc1 = lamc[col + 1];
#pragma unroll
                for (int rr = 0; rr < 2; rr++) {
                    size_t idx = (size_t)(row0 + rr * 8) * N + col;
                    float i0 = sigmoid_f(acc[mt][nt][rr * 2 + 0] + b0);
                    float i1 = sigmoid_f(acc[mt][nt][rr * 2 + 1] + b1);
                    float2 rv = *(const float2*)(Rbuf + idx);
                    float2 uv = *(const float2*)(Ubuf + idx);
                    float a0 = expf(lc0 * rv.x);
                    float a1 = expf(lc1 * rv.y);
                    float be0 = sqrtf(fmaxf(1.0f - a0 * a0, 1e-12f));
                    float be1 = sqrtf(fmaxf(1.0f - a1 * a1, 1e-12f));
                    *(float2*)(Aout + idx) = make_float2(a0, a1);
                    *(float2*)(C + idx) = make_float2(be0 * i0 * uv.x, be1 * i1 * uv.y);
                }
            } else {
#pragma unroll
                for (int rr = 0; rr < 2; rr++) {
                    float v0 = acc[mt][nt][rr * 2 + 0] + b0;
                    float v1 = acc[mt][nt][rr * 2 + 1] + b1;
                    if (act == 1) { v0 = gelu_f(v0); v1 = gelu_f(v1); }
                    else if (act == 2) { v0 = sigmoid_f(v0); v1 = sigmoid_f(v1); }
                    *(float2*)(C + (size_t)(row0 + rr * 8) * N + col) = make_float2(v0, v1);
                }
            }
        }
    }
}

// ---------------------------------------------------------------------------
// Transpose + tf32-round: dst[N][K] = round(src[K][N])
// Grid: (N/32, K/32), 256 threads.
// ---------------------------------------------------------------------------
__global__ void transpose_tf32(const float* __restrict__ src, float* __restrict__ dst,
                               int K, int N)
{
    __shared__ float t[32][33];
    int k0 = blockIdx.y * 32, n0 = blockIdx.x * 32;
    int tx = threadIdx.x & 31, ty = threadIdx.x >> 5;
#pragma unroll
    for (int i = 0; i < 32; i += 8)
        t[ty + i][tx] = src[(size_t)(k0 + ty + i) * N + n0 + tx];
    __syncthreads();
#pragma unroll
    for (int i = 0; i < 32; i += 8)
        dst[(size_t)(n0 + ty + i) * K + k0 + tx] = rnd_tf32(t[tx][ty + i]);
}

// ---------------------------------------------------------------------------
// tf32 rounding copy (element count multiple of 1024)
// ---------------------------------------------------------------------------
__global__ void round_tf32(const float* __restrict__ src, float* __restrict__ dst)
{
    int i = (blockIdx.x * blockDim.x + threadIdx.x) * 4;
    float4 v = *(const float4*)(src + i);
    v.x = rnd_tf32(v.x); v.y = rnd_tf32(v.y);
    v.z = rnd_tf32(v.z); v.w = rnd_tf32(v.w);
    *(float4*)(dst + i) = v;
}

// ---------------------------------------------------------------------------
// Causal depthwise conv1d (width 4, left pad 3); writes tf32-rounded output
// ---------------------------------------------------------------------------
__global__ void conv_kernel(const float* __restrict__ w, const float* __restrict__ cb)
{
    int i = blockIdx.x * blockDim.x + threadIdx.x;
    int h = i % HID;
    int s = (i / HID) % SEQ;
    const float* base = g_rin + (size_t)i;
    float acc = cb[h];
#pragma unroll
    for (int k = 0; k < 4; k++) {
        int t = s - 3 + k;
        if (t >= 0) acc = fmaf(w[k * HID + h], base[(long)(k - 3) * HID], acc);
    }
    g_conv[i] = rnd_tf32(acc);
}

__global__ void lamc_kernel(const float* __restrict__ lam)
{
    int h = blockIdx.x * blockDim.x + threadIdx.x;
    if (h < HID) g_lamc[h] = -8.0f * log1pf(expf(-lam[h]));
}

// ---------------------------------------------------------------------------
// Chunked scan (3 passes), chunk length 128, 16 chunks/sequence.
// ---------------------------------------------------------------------------
__global__ void scan_pass1()
{
    int idx = blockIdx.x * blockDim.x + threadIdx.x;
    int h = idx % HID;
    int t = idx / HID;
    int c = t % NCHUNK;
    int b = t / NCHUNK;
    size_t base = ((size_t)b * SEQ + (size_t)c * CLEN) * HID + h;
    float P = 1.0f, hs = 0.0f;
#pragma unroll 4
    for (int s = 0; s < CLEN; s++) {
        size_t o = base + (size_t)s * HID;
        float a = g_ra[o], d = g_ri[o];
        P *= a;
        hs = fmaf(a, hs, d);
    }
    size_t oo = ((size_t)b * NCHUNK + c) * HID + h;
    g_cp[oo] = P;
    g_ch[oo] = hs;
}

__global__ void scan_pass2()
{
    int idx = blockIdx.x * blockDim.x + threadIdx.x;
    if (idx >= BATCH * HID) return;
    int b = idx / HID, h = idx % HID;
    float hin = 0.0f;
#pragma unroll
    for (int c = 0; c < NCHUNK; c++) {
        size_t oo = ((size_t)b * NCHUNK + c) * HID + h;
        g_hin[oo] = hin;
        hin = fmaf(g_cp[oo], hin, g_ch[oo]);
    }
}

__global__ void scan_pass3()
{
    int idx = blockIdx.x * blockDim.x + threadIdx.x;
    int h = idx % HID;
    int t = idx / HID;
    int c = t % NCHUNK;
    int b = t / NCHUNK;
    size_t base = ((size_t)b * SEQ + (size_t)c * CLEN) * HID + h;
    float hs = g_hin[((size_t)b * NCHUNK + c) * HID + h];
#pragma unroll 4
    for (int s = 0; s < CLEN; s++) {
        size_t o = base + (size_t)s * HID;
        float a = g_ra[o], d = g_ri[o];
        hs = fmaf(a, hs, d);
        g_y[o] = rnd_tf32(g_left[o] * hs);
    }
}

// ---------------------------------------------------------------------------
// Launch
// ---------------------------------------------------------------------------
extern "C" void kernel_launch(void* const* d_in, const int* in_sizes, int n_in,
                              void* d_out, int out_size)
{
    const float* x      = (const float*)d_in[0];
    const float* Wl     = (const float*)d_in[1];
    const float* bl     = (const float*)d_in[2];
    const float* Wr     = (const float*)d_in[3];
    const float* br     = (const float*)d_in[4];
    const float* conv_w = (const float*)d_in[5];
    const float* conv_b = (const float*)d_in[6];
    const float* Wa     = (const float*)d_in[7];
    const float* ba     = (const float*)d_in[8];
    const float* Wi     = (const float*)d_in[9];
    const float* bi     = (const float*)d_in[10];
    const float* lam    = (const float*)d_in[11];
    const float* Wo     = (const float*)d_in[12];
    const float* bo     = (const float*)d_in[13];
    float* out = (float*)d_out;

    float *p_left, *p_rin, *p_conv, *p_ra, *p_ri, *p_y, *p_xr;
    float *p_wl, *p_wr, *p_wa, *p_wi, *p_wo, *p_lamc;
    cudaGetSymbolAddress((void**)&p_left, g_left);
    cudaGetSymbolAddress((void**)&p_rin,  g_rin);
    cudaGetSymbolAddress((void**)&p_conv, g_conv);
    cudaGetSymbolAddress((void**)&p_ra,   g_ra);
    cudaGetSymbolAddress((void**)&p_ri,   g_ri);
    cudaGetSymbolAddress((void**)&p_y,    g_y);
    cudaGetSymbolAddress((void**)&p_xr,   g_xr);
    cudaGetSymbolAddress((void**)&p_wl,   g_wl);
    cudaGetSymbolAddress((void**)&p_wr,   g_wr);
    cudaGetSymbolAddress((void**)&p_wa,   g_wa);
    cudaGetSymbolAddress((void**)&p_wi,   g_wi);
    cudaGetSymbolAddress((void**)&p_wo,   g_wo);
    cudaGetSymbolAddress((void**)&p_lamc, g_lamc);

    cudaFuncSetAttribute(gemm_tt<0>, cudaFuncAttributeMaxDynamicSharedMemorySize, SM_BYTES);
    cudaFuncSetAttribute(gemm_tt<2>, cudaFuncAttributeMaxDynamicSharedMemorySize, SM_BYTES);
    cudaFuncSetAttribute(gemm_tt<3>, cudaFuncAttributeMaxDynamicSharedMemorySize, SM_BYTES);
    cudaFuncSetAttribute(gemm_tt<4>, cudaFuncAttributeMaxDynamicSharedMemorySize, SM_BYTES);

    dim3 blk(256);
    dim3 gridHx2(2 * HID / 128, MROWS / 128);   // fused Wl+Wr
    dim3 gridH(HID / 128, MROWS / 128);
    dim3 gridO(OUTD / 128, MROWS / 128);
    int ew_blocks = (MROWS * HID) / 256;
    int sc_blocks = (BATCH * NCHUNK * HID) / 256;

    // 0) pre-round x; transpose+round all weights
    round_tf32<<<(MROWS * IND) / 1024, blk>>>(x, p_xr);
    transpose_tf32<<<dim3(HID / 32, IND / 32), blk>>>(Wl, p_wl, IND, HID);
    transpose_tf32<<<dim3(HID / 32, IND / 32), blk>>>(Wr, p_wr, IND, HID);
    transpose_tf32<<<dim3(HID / 32, HID / 32), blk>>>(Wa, p_wa, HID, HID);
    transpose_tf32<<<dim3(HID / 32, HID / 32), blk>>>(Wi, p_wi, HID, HID);
    transpose_tf32<<<dim3(OUTD / 32, HID / 32), blk>>>(Wo, p_wo, HID, OUTD);
    lamc_kernel<<<(HID + 255) / 256, blk>>>(lam);

    // 1) fused: left = gelu(x@Wl+bl) ; rin = x@Wr+br
    gemm_tt<4><<<gridHx2, blk, SM_BYTES>>>(p_xr, p_wl, bl, p_left, MROWS, HID, IND,
                                           nullptr, nullptr, nullptr, nullptr,
                                           p_wr, br, p_rin);

    // 2) causal depthwise conv (tf32-rounded output)
    conv_kernel<<<ew_blocks, blk>>>(conv_w, conv_b);

    // 3) r = sigmoid(conv@Wa+ba); then Wi-GEMM with fused gate epilogue
    gemm_tt<2><<<gridH, blk, SM_BYTES>>>(p_conv, p_wa, ba, p_ra, MROWS, HID, HID,
                                         nullptr, nullptr, nullptr, nullptr,
                                         nullptr, nullptr, nullptr);
    gemm_tt<3><<<gridH, blk, SM_BYTES>>>(p_conv, p_wi, bi, p_ri, MROWS, HID, HID,
                                         p_ra, p_conv, p_lamc, p_ra,
                                         nullptr, nullptr, nullptr);

    // 4) chunked scan + y = round(left*h)
    scan_pass1<<<sc_blocks, blk>>>();
    scan_pass2<<<(BATCH * HID + 255) / 256, blk>>>();
    scan_pass3<<<sc_blocks, blk>>>();

    // 5) out = y@Wo + bo
    gemm_tt<0><<<gridO, blk, SM_BYTES>>>(p_y, p_wo, bo, out, MROWS, OUTD, HID,
                                         nullptr, nullptr, nullptr, nullptr,
                                         nullptr, nullptr, nullptr);
}